// round 1
// baseline (speedup 1.0000x reference)
#include <cuda_runtime.h>

// ---------------------------------------------------------------------------
// TexturedSoftPhongShader fused kernel
// Inputs (metadata order):
//  0 texels        (N,H,W,K,3) f32
//  1 bary_coords   (N,H,W,K,3) f32
//  2 zbuf          (N,H,W,K)   f32
//  3 dists         (N,H,W,K)   f32
//  4 verts         (V,3)       f32   (unused: specular path is zero)
//  5 vertex_normals(V,3)       f32
//  6 gamma         (N,27)      f32
//  7 pix_to_face   (N,H,W,K)   i32
//  8 faces         (F,3)       i32
// Output: (N,H,W,4) f32
// ---------------------------------------------------------------------------

#define MAXF 70000

// Scratch: per-face, per-corner raw vertex normals, float4-padded for LDG.128.
// (Flip of x,y is folded into the SH coefficients, so store raw normals.)
__device__ float4 g_fn[MAXF * 3];

__global__ void prep_kernel(const int* __restrict__ faces,
                            const float* __restrict__ vn, int F) {
    int f = blockIdx.x * blockDim.x + threadIdx.x;
    if (f >= F) return;
    int i0 = faces[3 * f + 0];
    int i1 = faces[3 * f + 1];
    int i2 = faces[3 * f + 2];
    g_fn[3 * f + 0] = make_float4(vn[3 * i0], vn[3 * i0 + 1], vn[3 * i0 + 2], 0.f);
    g_fn[3 * f + 1] = make_float4(vn[3 * i1], vn[3 * i1 + 1], vn[3 * i1 + 2], 0.f);
    g_fn[3 * f + 2] = make_float4(vn[3 * i2], vn[3 * i2 + 1], vn[3 * i2 + 2], 0.f);
}

__global__ __launch_bounds__(256)
void shade_kernel(const float4* __restrict__ texels,
                  const float4* __restrict__ bary,
                  const float4* __restrict__ zbuf4,
                  const float4* __restrict__ dists4,
                  const int4*   __restrict__ p2f4,
                  const float*  __restrict__ gamma,
                  float4*       __restrict__ out,
                  int HW, int P) {
    // SH constants (double-precision values, rounded to f32)
    const float A0C0   = 0.8862269254527580f;   // pi * 1/sqrt(4pi) = sqrt(pi)/2
    const float A1C1   = 1.7724538509055159f;   // sqrt(pi)
    const float A2C2   = 2.4270323670f;         // (2pi/sqrt8)*(3 sqrt5 / sqrt(12pi))
    const float A2C2D0 = 0.7006239630f;         // A2C2 * 0.5/sqrt(3)

    const float SIGMA   = 1e-4f;
    const float GAMMA_B = 1e-4f;
    const float EPS     = 1e-10f;
    const float INV_SIGMA = 1.0f / SIGMA;       // matches f32 reference semantics
    const float INV_GAMMA = 1.0f / GAMMA_B;
    const float INV_ZR    = 1.0f / 99.0f;       // 1/(zfar - znear)

    // Per-block folded SH coefficients for this image.
    // lighting_c = C[0][c] + C[1][c]*my + C[2][c]*mz + C[3][c]*mx
    //            + C[4][c]*(mx*my) + C[5][c]*(my*mz) + C[6][c]*mz^2
    //            + C[7][c]*(mx*mz) + C[8][c]*(mx^2 - my^2)
    // where m is the interpolated RAW vertex normal (x,y flip folded in signs,
    // +0.8 bias and the -1 from (3nz^2-1) folded into C[0]).
    __shared__ float sC[9][3];
    int tid = threadIdx.x;
    int pix0 = blockIdx.x * 256;
    if (tid < 3) {
        int c = tid;
        int n0 = pix0 / HW;
        const float* gp = gamma + n0 * 27 + c * 9;
        float g0 = gp[0] + 0.8f;
        float g6 = gp[6];
        sC[0][c] = A0C0 * g0 - A2C2D0 * g6;
        sC[1][c] = A1C1 * gp[1];
        sC[2][c] = A1C1 * gp[2];
        sC[3][c] = A1C1 * gp[3];
        sC[4][c] = A2C2 * gp[4];
        sC[5][c] = A2C2 * gp[5];
        sC[6][c] = 3.0f * A2C2D0 * g6;
        sC[7][c] = A2C2 * gp[7];
        sC[8][c] = A2C2 * 0.5f * gp[8];
    }
    __syncthreads();

    int pix = pix0 + tid;
    if (pix >= P) return;

    float C[9][3];
#pragma unroll
    for (int i = 0; i < 9; i++)
#pragma unroll
        for (int c = 0; c < 3; c++) C[i][c] = sC[i][c];

    // Streaming loads (all 16B-aligned)
    float4 t0 = texels[pix * 3 + 0];
    float4 t1 = texels[pix * 3 + 1];
    float4 t2 = texels[pix * 3 + 2];
    float4 b0 = bary[pix * 3 + 0];
    float4 b1 = bary[pix * 3 + 1];
    float4 b2 = bary[pix * 3 + 2];
    float4 z4 = zbuf4[pix];
    float4 d4 = dists4[pix];
    int4   f4 = p2f4[pix];

    float tex[4][3] = {{t0.x, t0.y, t0.z}, {t0.w, t1.x, t1.y},
                       {t1.z, t1.w, t2.x}, {t2.y, t2.z, t2.w}};
    float bc[4][3]  = {{b0.x, b0.y, b0.z}, {b0.w, b1.x, b1.y},
                       {b1.z, b1.w, b2.x}, {b2.y, b2.z, b2.w}};
    float zv[4] = {z4.x, z4.y, z4.z, z4.w};
    float dv[4] = {d4.x, d4.y, d4.z, d4.w};
    int   fv[4] = {f4.x, f4.y, f4.z, f4.w};

    // Pass 1: z_inv and its max (init at EPS == clip lower bound)
    float zi[4];
    float zmax = EPS;
#pragma unroll
    for (int k = 0; k < 4; k++) {
        bool m = fv[k] >= 0;
        zi[k] = m ? (100.0f - zv[k]) * INV_ZR : 0.0f;
        zmax = fmaxf(zmax, zi[k]);
    }

    // Pass 2: fused weight + color accumulation
    float accR = 0.f, accG = 0.f, accB = 0.f;
    float wsum = 0.f;
    float oma = 1.f;   // prod(1 - prob)
#pragma unroll
    for (int k = 0; k < 4; k++) {
        if (fv[k] >= 0) {
            float prob = __fdividef(1.0f, 1.0f + __expf(dv[k] * INV_SIGMA));
            oma *= (1.0f - prob);
            float w = prob * __expf((zi[k] - zmax) * INV_GAMMA);
            wsum += w;

            const float4* fp = g_fn + 3 * fv[k];
            float4 v0 = fp[0];
            float4 v1 = fp[1];
            float4 v2 = fp[2];
            float mx = bc[k][0] * v0.x + bc[k][1] * v1.x + bc[k][2] * v2.x;
            float my = bc[k][0] * v0.y + bc[k][1] * v1.y + bc[k][2] * v2.y;
            float mz = bc[k][0] * v0.z + bc[k][1] * v1.z + bc[k][2] * v2.z;

            float pxy = mx * my;
            float pyz = my * mz;
            float pxz = mx * mz;
            float pzz = mz * mz;
            float pd  = fmaf(-my, my, mx * mx);   // mx^2 - my^2

            float Lr = C[0][0] + C[1][0]*my + C[2][0]*mz + C[3][0]*mx
                     + C[4][0]*pxy + C[5][0]*pyz + C[6][0]*pzz
                     + C[7][0]*pxz + C[8][0]*pd;
            float Lg = C[0][1] + C[1][1]*my + C[2][1]*mz + C[3][1]*mx
                     + C[4][1]*pxy + C[5][1]*pyz + C[6][1]*pzz
                     + C[7][1]*pxz + C[8][1]*pd;
            float Lb = C[0][2] + C[1][2]*my + C[2][2]*mz + C[3][2]*mx
                     + C[4][2]*pxy + C[5][2]*pyz + C[6][2]*pzz
                     + C[7][2]*pxz + C[8][2]*pd;

            accR = fmaf(w, Lr * tex[k][0], accR);
            accG = fmaf(w, Lg * tex[k][1], accG);
            accB = fmaf(w, Lb * tex[k][2], accB);
        }
    }

    float delta = fmaxf(__expf((EPS - zmax) * INV_GAMMA), EPS);
    float invden = __fdividef(1.0f, wsum + delta);
    float bg = delta * invden;   // BG = (1,1,1)

    float4 o;
    o.x = fmaf(accR, invden, bg);
    o.y = fmaf(accG, invden, bg);
    o.z = fmaf(accB, invden, bg);
    o.w = 1.0f - oma;
    out[pix] = o;
}

extern "C" void kernel_launch(void* const* d_in, const int* in_sizes, int n_in,
                              void* d_out, int out_size) {
    const float* texels = (const float*)d_in[0];
    const float* bary   = (const float*)d_in[1];
    const float* zbuf   = (const float*)d_in[2];
    const float* dists  = (const float*)d_in[3];
    // d_in[4] = verts, unused (specular color is identically zero)
    const float* vn     = (const float*)d_in[5];
    const float* gamma  = (const float*)d_in[6];
    const int*   p2f    = (const int*)d_in[7];
    const int*   faces  = (const int*)d_in[8];

    int F = in_sizes[8] / 3;
    if (F > MAXF) F = MAXF;
    int P = in_sizes[2] / 4;         // total pixels (K = 4)
    int N = in_sizes[6] / 27;
    int HW = P / N;

    prep_kernel<<<(F + 255) / 256, 256>>>(faces, vn, F);
    shade_kernel<<<(P + 255) / 256, 256>>>(
        (const float4*)texels, (const float4*)bary,
        (const float4*)zbuf, (const float4*)dists,
        (const int4*)p2f, gamma, (float4*)d_out, HW, P);
}